// round 12
// baseline (speedup 1.0000x reference)
#include <cuda_runtime.h>
#include <math.h>

#define NH 8
#define NB 2
#define NSEQ 384
#define NCZ 128
#define NCH 144            // per-head channels: 128 mv + 16 scalar
#define BIGF 100000.0f
#define LNEPS 1e-5f

#define QT 16              // q tile
#define JTT 32             // j tile
#define NJT (NSEQ/JTT)     // 12

// attn smem strides (floats)
#define SQDP 36            // sQd [144][36]: 16 q duplicated pairs (32 fl) + pad
#define SKP 36             // sK  [144][36]: 32 j + pad
#define SVP 148            // sV  [32][148]
#define SPP 36             // sP  [16][36]
#define ATTN_SMEM_FLOATS (144*SQDP + 144*SKP + 32*SVP + 16*SPP)  // 15680 fl = 62.7 KB

// Scratch (no cudaMalloc allowed)
__device__ float g_Q[NB*NH*NCH*NSEQ];    // channel-major [b][h][c][n]
__device__ float g_K[NB*NH*NCH*NSEQ];    // channel-major [b][h][c][n]
__device__ float g_V[NB*NH*NSEQ*NCH];    // row-major    [b][h][n][c]
__device__ float g_bias[NB*NH*NSEQ*NSEQ];
__device__ float g_Hb[NB*NSEQ*NH*NCH];

typedef unsigned long long ull;

// ---------------- f32x2 packed helpers ----------------
__device__ __forceinline__ void fma2(ull& d, ull a, ull b){
    asm("fma.rn.f32x2 %0, %1, %2, %0;" : "+l"(d) : "l"(a), "l"(b));
}
__device__ __forceinline__ void mul2(ull& d, ull a){
    asm("mul.rn.f32x2 %0, %0, %1;" : "+l"(d) : "l"(a));
}
__device__ __forceinline__ ull pack2(float lo, float hi){
    ull d;
    asm("mov.b64 %0, {%1, %2};" : "=l"(d) : "f"(lo), "f"(hi));
    return d;
}
__device__ __forceinline__ void unpack2(ull d, float& lo, float& hi){
    asm("mov.b64 {%0, %1}, %2;" : "=f"(lo), "=f"(hi) : "l"(d));
}

// ---------------- reductions ----------------
__device__ __forceinline__ float warpSum(float v){
#pragma unroll
    for(int o=16;o;o>>=1) v += __shfl_xor_sync(0xffffffffu, v, o);
    return v;
}
__device__ __forceinline__ float blockSum8(float v, float* red){
    int lane = threadIdx.x & 31, w = threadIdx.x >> 5;
    v = warpSum(v);
    if(lane==0) red[w] = v;
    __syncthreads();
    if(threadIdx.x < 32){
        float r = (lane < 8) ? red[lane] : 0.0f;
        r = warpSum(r);
        if(lane==0) red[0] = r;
    }
    __syncthreads();
    float r = red[0];
    __syncthreads();
    return r;
}
__device__ __forceinline__ float grpMax(float v){
#pragma unroll
    for(int o=8;o;o>>=1) v = fmaxf(v, __shfl_xor_sync(0xffffffffu, v, o));
    return v;
}
__device__ __forceinline__ float grpSum(float v){
#pragma unroll
    for(int o=8;o;o>>=1) v += __shfl_xor_sync(0xffffffffu, v, o);
    return v;
}

// ---------------- probe: shifts the fixed ncu capture slot ----------------
__global__ void probe_kernel(){}

// ---------------- Kernel A: pln + QKV projections + rope ----------------
__global__ void qkv_kernel(const float* __restrict__ mv, const float* __restrict__ sca,
                           const float* __restrict__ Wq_mv, const float* __restrict__ Wq_s,
                           const float* __restrict__ Wkv_mv, const float* __restrict__ Wkv_s){
    int bn = blockIdx.x;
    int b = bn / NSEQ, n = bn % NSEQ;
    int t = threadIdx.x;
    __shared__ float mvn[256];
    __shared__ float scn[64];
    __shared__ float qs[128], ks[128], vs[128];
    __shared__ float red[32];
    const float scl = 1.0f/12.0f;

    float x = mv[(size_t)bn*256 + t];
    float s1 = blockSum8(x, red);
    float s2 = blockSum8(x*x, red);
    float m  = s1 * (1.0f/256.0f);
    float vr = s2 * (1.0f/256.0f) - m*m;
    mvn[t] = (x - m) * rsqrtf(vr + LNEPS);

    float y = (t < 64) ? sca[(size_t)bn*64 + t] : 0.0f;
    float t1 = blockSum8(y, red);
    float t2 = blockSum8(y*y, red);
    float m2 = t1 * (1.0f/64.0f);
    float v2 = t2 * (1.0f/64.0f) - m2*m2;
    float rs2 = rsqrtf(v2 + LNEPS);
    if(t < 64) scn[t] = (y - m2) * rs2;
    __syncthreads();

    for(int idx = t; idx < 1024; idx += 256){
        int o = idx >> 4, i = idx & 15;
        float a = 0.0f;
#pragma unroll
        for(int c = 0; c < 16; c++) a += mvn[c*16 + i] * Wq_mv[o*16 + c];
        int hh = o & 7, mm = o >> 3;
        g_Q[((size_t)(b*NH + hh)*NCH + mm*16 + i)*NSEQ + n] = a * scl;
    }
    for(int idx = t; idx < 2048; idx += 256){
        int o = idx >> 4, i = idx & 15;
        float a = 0.0f;
#pragma unroll
        for(int c = 0; c < 16; c++) a += mvn[c*16 + i] * Wkv_mv[o*16 + c];
        int kv = o >> 6, rr = o & 63, hh = rr & 7, mm = rr >> 3;
        if(kv == 0) g_K[((size_t)(b*NH + hh)*NCH + mm*16 + i)*NSEQ + n] = a;
        else        g_V[((size_t)(b*NH + hh)*NSEQ + n)*NCH + mm*16 + i] = a;
    }
    if(t < 128){
        float a = 0.0f;
#pragma unroll
        for(int c = 0; c < 64; c++) a += scn[c] * Wq_s[t*64 + c];
        qs[t] = a;
    }
    {
        float a = 0.0f;
#pragma unroll
        for(int c = 0; c < 64; c++) a += scn[c] * Wkv_s[t*64 + c];
        int kv = t >> 7, rr = t & 127;
        if(kv == 0) ks[rr] = a; else vs[rr] = a;
    }
    __syncthreads();

    if(t < 128){
        int hh = t & 7, ss = t >> 3;
        g_V[((size_t)(b*NH + hh)*NSEQ + n)*NCH + 128 + ss] = vs[t];
    }
    if(t < 64){
        int hh = t & 7, p = t >> 3;
        float ang = (float)n * exp2f(-1.5f * (float)p);
        float cs = cosf(ang), sn = sinf(ang);
        float x1 = qs[(2*p)*8 + hh], x2 = qs[(2*p+1)*8 + hh];
        size_t base = ((size_t)(b*NH + hh)*NCH + 128);
        g_Q[(base + 2*p  )*NSEQ + n] = (x1*cs - x2*sn) * scl;
        g_Q[(base + 2*p+1)*NSEQ + n] = (x1*sn + x2*cs) * scl;
    } else if(t < 128){
        int u = t - 64;
        int hh = u & 7, p = u >> 3;
        float ang = (float)n * exp2f(-1.5f * (float)p);
        float cs = cosf(ang), sn = sinf(ang);
        float x1 = ks[(2*p)*8 + hh], x2 = ks[(2*p+1)*8 + hh];
        size_t base = ((size_t)(b*NH + hh)*NCH + 128);
        g_K[(base + 2*p  )*NSEQ + n] = x1*cs - x2*sn;
        g_K[(base + 2*p+1)*NSEQ + n] = x1*sn + x2*cs;
    }
}

// ---------------- Kernel B: bias (R8 tiled version) ----------------
__global__ __launch_bounds__(256) void bias_kernel(
        const float* __restrict__ pz, const unsigned int* __restrict__ msk,
        const float* __restrict__ gamma, const float* __restrict__ beta,
        const float* __restrict__ Wpb){
    __shared__ float sZ[32*132];
    __shared__ float sA[8*132];
    __shared__ float sG[8], sB[8];
    __shared__ float sM[32];
    __shared__ float sR[32];
    __shared__ float sMask[32];

    int t = threadIdx.x;
    int lane = t & 31, w = t >> 5;
    int pid0 = blockIdx.x * 32;
    int b  = pid0 / (NSEQ*NSEQ);
    int r0 = pid0 % (NSEQ*NSEQ);
    int i  = r0 / NSEQ;
    int j0 = r0 % NSEQ;

    const float4* zg = (const float4*)(pz + (size_t)pid0 * NCZ);
    for(int i4 = t; i4 < 1024; i4 += 256){
        int r = i4 >> 5, c4 = i4 & 31;
        *(float4*)(sZ + r*132 + c4*4) = zg[i4];
    }
    for(int idx = t; idx < 1024; idx += 256){
        int h = idx >> 7, c = idx & 127;
        sA[h*132 + c] = gamma[c] * Wpb[h*NCZ + c];
    }
    {
        float gs = 0.f, bs = 0.f;
#pragma unroll
        for(int k = 0; k < 4; k++){
            int c = lane + 32*k;
            float wv = Wpb[w*NCZ + c];
            gs += gamma[c]*wv;
            bs += beta[c]*wv;
        }
        gs = warpSum(gs); bs = warpSum(bs);
        if(lane == 0){ sG[w] = gs; sB[w] = bs; }
    }
    if(t < 32) sMask[t] = (msk[pid0 + t] != 0u) ? 0.0f : BIGF;
    __syncthreads();

#pragma unroll
    for(int rr = 0; rr < 4; rr++){
        int p = w*4 + rr;
        float4 z4 = *(const float4*)(sZ + p*132 + lane*4);
        float s1 = z4.x + z4.y + z4.z + z4.w;
        float s2 = z4.x*z4.x + z4.y*z4.y + z4.z*z4.z + z4.w*z4.w;
        s1 = warpSum(s1); s2 = warpSum(s2);
        if(lane == 0){
            float m = s1 * (1.0f/NCZ);
            float v = s2 * (1.0f/NCZ) - m*m;
            sM[p] = m;
            sR[p] = rsqrtf(v + LNEPS);
        }
    }
    __syncthreads();

    {
        int p = t >> 3, h = t & 7;
        const float4* zp = (const float4*)(sZ + p*132);
        const float4* ap = (const float4*)(sA + h*132);
        float acc = 0.f;
#pragma unroll
        for(int c4 = 0; c4 < 32; c4++){
            float4 z4 = zp[c4], a4 = ap[c4];
            acc += z4.x*a4.x + z4.y*a4.y + z4.z*a4.z + z4.w*a4.w;
        }
        float out = sR[p]*(acc - sM[p]*sG[h]) + sB[h] + sMask[p];
        g_bias[((size_t)(b*NH + h)*NSEQ + i)*NSEQ + j0 + p] = out;
    }
}

// ---------------- Kernel C: attention, f32x2, QT=16 JTT=32, 3 blocks/SM ----------------
// 256 threads: r = t>>4 (one q row), tx = t&15 (QK cols tx*2..+1; AV ch tx*8..+7, 128+tx)
__global__ __launch_bounds__(256, 3) void attn_kernel(){
    extern __shared__ float smem[];
    float* sQd = smem;                      // [144][SQDP] duplicated q pairs
    float* sK  = sQd + 144*SQDP;            // [144][SKP]
    float* sV  = sK  + 144*SKP;             // [32][SVP]
    float* sP  = sV  + 32*SVP;              // [16][SPP]

    int qt = blockIdx.x, h = blockIdx.y, b = blockIdx.z;
    int t = threadIdx.x;
    int r = t >> 4, tx = t & 15;
    int q0 = qt * QT;
    size_t bh = (size_t)(b*NH + h);

    const float* Qg = g_Q + bh*NCH*NSEQ;
    const float* Kg = g_K + bh*NCH*NSEQ;
    const float* Vg = g_V + bh*NSEQ*NCH;
    const float* Bg = g_bias + (bh*NSEQ + q0)*NSEQ;

    // load Q tile duplicated: sQd[c][2q],[2q+1] = Q[c][q0+q], 16 q per channel
    for(int idx = t; idx < 144*16; idx += 256){
        int c = idx >> 4, q = idx & 15;
        float v = Qg[(size_t)c*NSEQ + q0 + q];
        sQd[c*SQDP + 2*q]   = v;
        sQd[c*SQDP + 2*q+1] = v;
    }

    float mr = -1e30f, lr = 0.f;
    ull O[4];
    float e = 0.f;                          // extra channel 128+tx
    ull zero = pack2(0.f, 0.f);
#pragma unroll
    for(int k = 0; k < 4; k++) O[k] = zero;

    for(int jt = 0; jt < NJT; jt++){
        int j0 = jt * JTT;
        __syncthreads();
        // K tile: 144 ch x 32 j
        for(int i4 = t; i4 < 144*8; i4 += 256){
            int c = i4 >> 3, jj = i4 & 7;
            *(float4*)(sK + c*SKP + jj*4) = *(const float4*)(Kg + (size_t)c*NSEQ + j0 + jj*4);
        }
        // V tile: 32 j x 144 ch
        for(int i4 = t; i4 < 32*36; i4 += 256){
            int rr = i4/36, c4 = i4%36;
            *(float4*)(sV + rr*SVP + c4*4) = *(const float4*)(Vg + (size_t)(j0+rr)*NCH + c4*4);
        }
        __syncthreads();

        // QK: packed; S = (s[r][tx*2], s[r][tx*2+1])
        ull S = zero;
#pragma unroll 8
        for(int c = 0; c < NCH; c++){
            ull qa2 = *(const ull*)(sQd + c*SQDP + 2*r);
            ull k2  = *(const ull*)(sK  + c*SKP  + tx*2);
            fma2(S, qa2, k2);
        }
        float s0, s1;
        unpack2(S, s0, s1);
        {
            float2 b2 = *(const float2*)(Bg + (size_t)r*NSEQ + j0 + tx*2);
            s0 += b2.x; s1 += b2.y;
        }
        // online softmax
        float nm = fmaxf(mr, grpMax(fmaxf(s0, s1)));
        float a = __expf(mr - nm);
        float p0 = __expf(s0 - nm), p1 = __expf(s1 - nm);
        lr = lr*a + grpSum(p0 + p1);
        mr = nm;
        ull a2 = pack2(a, a);
#pragma unroll
        for(int k = 0; k < 4; k++) mul2(O[k], a2);
        e *= a;
        *(float2*)(sP + r*SPP + tx*2) = make_float2(p0, p1);
        __syncthreads();

        // AV: packed channels tx*8..+7 + scalar 128+tx
#pragma unroll 4
        for(int jj = 0; jj < JTT; jj++){
            float p = sP[r*SPP + jj];
            ull pk = pack2(p, p);
            const float* vr = sV + jj*SVP;
            ulonglong2 va = *(const ulonglong2*)(vr + tx*8);
            ulonglong2 vb = *(const ulonglong2*)(vr + tx*8 + 4);
            fma2(O[0], pk, va.x); fma2(O[1], pk, va.y);
            fma2(O[2], pk, vb.x); fma2(O[3], pk, vb.y);
            e += p * vr[128 + tx];
        }
    }

    float inv = 1.0f/lr;
    ull i2 = pack2(inv, inv);
#pragma unroll
    for(int k = 0; k < 4; k++) mul2(O[k], i2);
    float* og = g_Hb + ((size_t)(b*NSEQ + q0 + r)*NH + h)*NCH;
    *(ulonglong2*)(og + tx*8)     = make_ulonglong2(O[0], O[1]);
    *(ulonglong2*)(og + tx*8 + 4) = make_ulonglong2(O[2], O[3]);
    og[128 + tx] = e*inv;
}

// ---------------- Kernel D: output projections ----------------
__global__ __launch_bounds__(256) void out_kernel(
        const float* __restrict__ Wo_mv, const float* __restrict__ Wo_s,
        float* __restrict__ out){
    int bn = blockIdx.x;
    int t = threadIdx.x;
    __shared__ float wmv[16*64];
    __shared__ float ws [64*128];
    __shared__ float hrow[NH*NCH];

    for(int i = t; i < 1024; i += 256) wmv[i] = Wo_mv[i];
    for(int i4 = t; i4 < 2048; i4 += 256)
        *(float4*)(ws + i4*4) = ((const float4*)Wo_s)[i4];
    for(int i4 = t; i4 < 288; i4 += 256)
        *(float4*)(hrow + i4*4) = ((const float4*)(g_Hb + (size_t)bn*NH*NCH))[i4];
    __syncthreads();

    {
        int o = t >> 4, i = t & 15;
        float acc = 0.0f;
#pragma unroll
        for(int hh = 0; hh < 8; hh++)
#pragma unroll
            for(int mm = 0; mm < 8; mm++)
                acc += hrow[hh*NCH + mm*16 + i] * wmv[o*64 + hh*8 + mm];
        out[(size_t)bn*256 + t] = acc;
    }
    if(t < 64){
        float acc = 0.0f;
#pragma unroll
        for(int hh = 0; hh < 8; hh++)
#pragma unroll
            for(int ss = 0; ss < 16; ss++)
                acc += hrow[hh*NCH + 128 + ss] * ws[t*128 + hh*16 + ss];
        out[(size_t)NB*NSEQ*256 + (size_t)bn*64 + t] = acc;
    }
}

// ---------------- launch ----------------
extern "C" void kernel_launch(void* const* d_in, const int* in_sizes, int n_in,
                              void* d_out, int out_size){
    const float* mv    = (const float*)d_in[0];
    const float* sca   = (const float*)d_in[1];
    const float* pz    = (const float*)d_in[2];
    const unsigned int* mask = (const unsigned int*)d_in[3];
    const float* Wq_mv = (const float*)d_in[4];
    const float* Wq_s  = (const float*)d_in[5];
    const float* Wkv_mv= (const float*)d_in[6];
    const float* Wkv_s = (const float*)d_in[7];
    const float* Wo_mv = (const float*)d_in[8];
    const float* Wo_s  = (const float*)d_in[9];
    const float* lng   = (const float*)d_in[10];
    const float* lnb   = (const float*)d_in[11];
    const float* Wpb   = (const float*)d_in[12];

    cudaFuncSetAttribute(attn_kernel, cudaFuncAttributeMaxDynamicSharedMemorySize,
                         ATTN_SMEM_FLOATS * (int)sizeof(float));

    probe_kernel<<<1, 32>>>();   // keeps ncu's capture slot on attn for a direct A/B
    qkv_kernel<<<NB*NSEQ, 256>>>(mv, sca, Wq_mv, Wq_s, Wkv_mv, Wkv_s);
    bias_kernel<<<(NB*NSEQ*NSEQ)/32, 256>>>(pz, mask, lng, lnb, Wpb);
    attn_kernel<<<dim3(NSEQ/QT, NH, NB), 256, ATTN_SMEM_FLOATS*sizeof(float)>>>();
    out_kernel<<<NB*NSEQ, 256>>>(Wo_mv, Wo_s, (float*)d_out);
}

// round 14
// speedup vs baseline: 1.2126x; 1.2126x over previous
#include <cuda_runtime.h>
#include <math.h>

#define NH 8
#define NB 2
#define NSEQ 384
#define NCZ 128
#define NCH 144            // per-head channels: 128 mv + 16 scalar
#define BIGF 100000.0f
#define LNEPS 1e-5f

#define QT 32              // q tile (R11 config)
#define JTT 32             // j tile
#define NJT (NSEQ/JTT)     // 12
#define NSPLIT 2           // j-splits
#define JT_PER_SPLIT (NJT/NSPLIT)  // 6

// attn smem strides (floats) — R11 layout
#define SQDP 68            // sQd [144][68]: 32 q duplicated pairs (64 fl) + pad
#define SKP 36             // sK  [144][36]
#define SVP 148            // sV  [32][148]
#define SPP 36             // sP  [32][36]
#define ATTN_SMEM_FLOATS (144*SQDP + 144*SKP + 32*SVP + 32*SPP)  // 20864 fl = 83.5 KB

#define PART_STRIDE 148    // per (js,bh,q): O[144], m, l, pad

// Scratch (no cudaMalloc allowed)
__device__ float g_Q[NB*NH*NCH*NSEQ];    // channel-major [b][h][c][n]
__device__ float g_K[NB*NH*NCH*NSEQ];    // channel-major [b][h][c][n]
__device__ float g_V[NB*NH*NSEQ*NCH];    // row-major    [b][h][n][c]
__device__ float g_bias[NB*NH*NSEQ*NSEQ];
__device__ float g_part[NSPLIT*NB*NH*NSEQ*PART_STRIDE];   // unnormalized partials
__device__ float g_Hb[NB*NSEQ*NH*NCH];

typedef unsigned long long ull;

// ---------------- f32x2 packed helpers ----------------
__device__ __forceinline__ void fma2(ull& d, ull a, ull b){
    asm("fma.rn.f32x2 %0, %1, %2, %0;" : "+l"(d) : "l"(a), "l"(b));
}
__device__ __forceinline__ void mul2(ull& d, ull a){
    asm("mul.rn.f32x2 %0, %0, %1;" : "+l"(d) : "l"(a));
}
__device__ __forceinline__ ull pack2(float lo, float hi){
    ull d;
    asm("mov.b64 %0, {%1, %2};" : "=l"(d) : "f"(lo), "f"(hi));
    return d;
}
__device__ __forceinline__ void unpack2(ull d, float& lo, float& hi){
    asm("mov.b64 {%0, %1}, %2;" : "=f"(lo), "=f"(hi) : "l"(d));
}

// ---------------- reductions ----------------
__device__ __forceinline__ float warpSum(float v){
#pragma unroll
    for(int o=16;o;o>>=1) v += __shfl_xor_sync(0xffffffffu, v, o);
    return v;
}
__device__ __forceinline__ float blockSum8(float v, float* red){
    int lane = threadIdx.x & 31, w = threadIdx.x >> 5;
    v = warpSum(v);
    if(lane==0) red[w] = v;
    __syncthreads();
    if(threadIdx.x < 32){
        float r = (lane < 8) ? red[lane] : 0.0f;
        r = warpSum(r);
        if(lane==0) red[0] = r;
    }
    __syncthreads();
    float r = red[0];
    __syncthreads();
    return r;
}
__device__ __forceinline__ float grpMax(float v){
#pragma unroll
    for(int o=8;o;o>>=1) v = fmaxf(v, __shfl_xor_sync(0xffffffffu, v, o));
    return v;
}
__device__ __forceinline__ float grpSum(float v){
#pragma unroll
    for(int o=8;o;o>>=1) v += __shfl_xor_sync(0xffffffffu, v, o);
    return v;
}
// reduce over 16-lane half (xor widths < 16 stay within the half)
__device__ __forceinline__ float halfSum(float v){
#pragma unroll
    for(int o=8;o;o>>=1) v += __shfl_xor_sync(0xffffffffu, v, o);
    return v;
}

// ---------------- probe: keeps ncu capture slot aligned ----------------
__global__ void probe_kernel(){}

// ---------------- Kernel A: pln + QKV projections + rope ----------------
__global__ void qkv_kernel(const float* __restrict__ mv, const float* __restrict__ sca,
                           const float* __restrict__ Wq_mv, const float* __restrict__ Wq_s,
                           const float* __restrict__ Wkv_mv, const float* __restrict__ Wkv_s){
    int bn = blockIdx.x;
    int b = bn / NSEQ, n = bn % NSEQ;
    int t = threadIdx.x;
    __shared__ float mvn[256];
    __shared__ float scn[64];
    __shared__ float qs[128], ks[128], vs[128];
    __shared__ float red[32];
    const float scl = 1.0f/12.0f;

    float x = mv[(size_t)bn*256 + t];
    float s1 = blockSum8(x, red);
    float s2 = blockSum8(x*x, red);
    float m  = s1 * (1.0f/256.0f);
    float vr = s2 * (1.0f/256.0f) - m*m;
    mvn[t] = (x - m) * rsqrtf(vr + LNEPS);

    float y = (t < 64) ? sca[(size_t)bn*64 + t] : 0.0f;
    float t1 = blockSum8(y, red);
    float t2 = blockSum8(y*y, red);
    float m2 = t1 * (1.0f/64.0f);
    float v2 = t2 * (1.0f/64.0f) - m2*m2;
    float rs2 = rsqrtf(v2 + LNEPS);
    if(t < 64) scn[t] = (y - m2) * rs2;
    __syncthreads();

    for(int idx = t; idx < 1024; idx += 256){
        int o = idx >> 4, i = idx & 15;
        float a = 0.0f;
#pragma unroll
        for(int c = 0; c < 16; c++) a += mvn[c*16 + i] * Wq_mv[o*16 + c];
        int hh = o & 7, mm = o >> 3;
        g_Q[((size_t)(b*NH + hh)*NCH + mm*16 + i)*NSEQ + n] = a * scl;
    }
    for(int idx = t; idx < 2048; idx += 256){
        int o = idx >> 4, i = idx & 15;
        float a = 0.0f;
#pragma unroll
        for(int c = 0; c < 16; c++) a += mvn[c*16 + i] * Wkv_mv[o*16 + c];
        int kv = o >> 6, rr = o & 63, hh = rr & 7, mm = rr >> 3;
        if(kv == 0) g_K[((size_t)(b*NH + hh)*NCH + mm*16 + i)*NSEQ + n] = a;
        else        g_V[((size_t)(b*NH + hh)*NSEQ + n)*NCH + mm*16 + i] = a;
    }
    if(t < 128){
        float a = 0.0f;
#pragma unroll
        for(int c = 0; c < 64; c++) a += scn[c] * Wq_s[t*64 + c];
        qs[t] = a;
    }
    {
        float a = 0.0f;
#pragma unroll
        for(int c = 0; c < 64; c++) a += scn[c] * Wkv_s[t*64 + c];
        int kv = t >> 7, rr = t & 127;
        if(kv == 0) ks[rr] = a; else vs[rr] = a;
    }
    __syncthreads();

    if(t < 128){
        int hh = t & 7, ss = t >> 3;
        g_V[((size_t)(b*NH + hh)*NSEQ + n)*NCH + 128 + ss] = vs[t];
    }
    if(t < 64){
        int hh = t & 7, p = t >> 3;
        float ang = (float)n * exp2f(-1.5f * (float)p);
        float cs = cosf(ang), sn = sinf(ang);
        float x1 = qs[(2*p)*8 + hh], x2 = qs[(2*p+1)*8 + hh];
        size_t base = ((size_t)(b*NH + hh)*NCH + 128);
        g_Q[(base + 2*p  )*NSEQ + n] = (x1*cs - x2*sn) * scl;
        g_Q[(base + 2*p+1)*NSEQ + n] = (x1*sn + x2*cs) * scl;
    } else if(t < 128){
        int u = t - 64;
        int hh = u & 7, p = u >> 3;
        float ang = (float)n * exp2f(-1.5f * (float)p);
        float cs = cosf(ang), sn = sinf(ang);
        float x1 = ks[(2*p)*8 + hh], x2 = ks[(2*p+1)*8 + hh];
        size_t base = ((size_t)(b*NH + hh)*NCH + 128);
        g_K[(base + 2*p  )*NSEQ + n] = x1*cs - x2*sn;
        g_K[(base + 2*p+1)*NSEQ + n] = x1*sn + x2*cs;
    }
}

// ---------------- Kernel B: bias, register-resident, 16-lane teams ----------------
// 256 thr = 8 warps. Warp iteration = 2 pairs: lanes 0-15 -> p0, 16-31 -> p1.
// Lane (l = lane&15) owns channels l*8..l*8+7 in registers; A = gamma*W in regs.
// 8 iterations... ITER=4 iterations x 2 pairs = 8 pairs/warp, 64/block.
#define BPW 8   // pairs per warp
__global__ __launch_bounds__(256) void bias_kernel(
        const float* __restrict__ pz, const unsigned int* __restrict__ msk,
        const float* __restrict__ gamma, const float* __restrict__ beta,
        const float* __restrict__ Wpb){
    __shared__ float sGB[16];   // G[0..7], B[8..15]

    int t = threadIdx.x;
    int lane = t & 31, w = t >> 5;
    int l = lane & 15;          // lane within half
    int half = lane >> 4;       // 0 -> p0, 1 -> p1

    // G_h, B_h (warp w -> head w)
    {
        float4 g4 = ((const float4*)gamma)[lane];
        float4 b4 = ((const float4*)beta)[lane];
        float4 w4 = ((const float4*)(Wpb + w*NCZ))[lane];
        float gs = g4.x*w4.x + g4.y*w4.y + g4.z*w4.z + g4.w*w4.w;
        float bs = b4.x*w4.x + b4.y*w4.y + b4.z*w4.z + b4.w*w4.w;
        gs = warpSum(gs); bs = warpSum(bs);
        if(lane == 0){ sGB[w] = gs; sGB[8+w] = bs; }
    }

    // A[h][k] = gamma[l*8+k] * Wpb[h][l*8+k] in registers
    float A[8][8];
    {
        float4 ga = ((const float4*)(gamma + l*8))[0];
        float4 gb = ((const float4*)(gamma + l*8))[1];
#pragma unroll
        for(int h = 0; h < 8; h++){
            float4 wa = ((const float4*)(Wpb + h*NCZ + l*8))[0];
            float4 wb = ((const float4*)(Wpb + h*NCZ + l*8))[1];
            A[h][0]=ga.x*wa.x; A[h][1]=ga.y*wa.y; A[h][2]=ga.z*wa.z; A[h][3]=ga.w*wa.w;
            A[h][4]=gb.x*wb.x; A[h][5]=gb.y*wb.y; A[h][6]=gb.z*wb.z; A[h][7]=gb.w*wb.w;
        }
    }
    __syncthreads();

    bool b3 = (l & 8), b2 = (l & 4), b1 = (l & 2);
    int hmine = (b3?4:0) + (b2?2:0) + (b1?1:0);
    float Gh = sGB[hmine], Bh = sGB[8+hmine];

    int base = (blockIdx.x*8 + w) * BPW;

#pragma unroll
    for(int it = 0; it < BPW/2; it++){
        int myPair = base + 2*it + half;

        // load my 8 channels
        float4 za = ((const float4*)(pz + (size_t)myPair*NCZ + l*8))[0];
        float4 zb = ((const float4*)(pz + (size_t)myPair*NCZ + l*8))[1];
        float z0=za.x, z1=za.y, z2=za.z, z3=za.w;
        float z4=zb.x, z5=zb.y, z6=zb.z, z7=zb.w;

        // LN stats over the 16-lane half
        float s1 = ((z0+z1)+(z2+z3)) + ((z4+z5)+(z6+z7));
        float s2 = (z0*z0+z1*z1+z2*z2+z3*z3) + (z4*z4+z5*z5+z6*z6+z7*z7);
        s1 = halfSum(s1);
        s2 = halfSum(s2);
        float m  = s1 * (1.0f/NCZ);
        float vr = s2 * (1.0f/NCZ) - m*m;
        float rs = rsqrtf(vr + LNEPS);

        // per-lane partial head dots (all in registers)
        float v[8];
#pragma unroll
        for(int h = 0; h < 8; h++)
            v[h] = z0*A[h][0] + z1*A[h][1] + z2*A[h][2] + z3*A[h][3]
                 + z4*A[h][4] + z5*A[h][5] + z6*A[h][6] + z7*A[h][7];

        // split butterfly over 16 lanes: 8 head-sums in 8 shuffles
#pragma unroll
        for(int k = 0; k < 4; k++){
            float send = b3 ? v[k] : v[k+4];
            float recv = __shfl_xor_sync(0xffffffffu, send, 8);
            v[k] = (b3 ? v[k+4] : v[k]) + recv;
        }
#pragma unroll
        for(int k = 0; k < 2; k++){
            float send = b2 ? v[k] : v[k+2];
            float recv = __shfl_xor_sync(0xffffffffu, send, 4);
            v[k] = (b2 ? v[k+2] : v[k]) + recv;
        }
        {
            float send = b1 ? v[0] : v[1];
            float recv = __shfl_xor_sync(0xffffffffu, send, 2);
            v[0] = (b1 ? v[1] : v[0]) + recv;
        }
        v[0] += __shfl_xor_sync(0xffffffffu, v[0], 1);

        float mterm = (msk[myPair] != 0u) ? 0.0f : BIGF;
        float outv = rs*(v[0] - m*Gh) + Bh + mterm;

        if((l & 1) == 0){
            int b  = myPair / (NSEQ*NSEQ);
            int r  = myPair - b*(NSEQ*NSEQ);
            int i  = r / NSEQ;
            int j  = r - i*NSEQ;
            g_bias[((size_t)(b*NH + hmine)*NSEQ + i)*NSEQ + j] = outv;
        }
    }
}

// ---------------- Kernel C: attention, R11 body + j-split partials ----------------
// grid (12 qt, 16 bh, 2 js). 256 thr: ty rowpair, tx cols/channels.
__global__ __launch_bounds__(256, 2) void attn_kernel(){
    extern __shared__ float smem[];
    float* sQd = smem;                      // [144][SQDP]
    float* sK  = sQd + 144*SQDP;            // [144][SKP]
    float* sV  = sK  + 144*SKP;             // [32][SVP]
    float* sP  = sV  + 32*SVP;              // [32][SPP]

    int qt = blockIdx.x, bh = blockIdx.y, js = blockIdx.z;
    int t = threadIdx.x;
    int ty = t >> 4, tx = t & 15;
    int q0 = qt * QT;

    const float* Qg = g_Q + (size_t)bh*NCH*NSEQ;
    const float* Kg = g_K + (size_t)bh*NCH*NSEQ;
    const float* Vg = g_V + (size_t)bh*NSEQ*NCH;
    const float* Bg = g_bias + ((size_t)bh*NSEQ + q0)*NSEQ;

    for(int idx = t; idx < 144*32; idx += 256){
        int c = idx >> 5, q = idx & 31;
        float v = Qg[(size_t)c*NSEQ + q0 + q];
        sQd[c*SQDP + 2*q]   = v;
        sQd[c*SQDP + 2*q+1] = v;
    }

    int r0 = ty*2, r1 = ty*2 + 1;
    float m0 = -1e30f, m1 = -1e30f, l0 = 0.f, l1 = 0.f;
    ull O0[4], O1[4];
    float e0 = 0.f, e1 = 0.f;
    ull zero = pack2(0.f, 0.f);
#pragma unroll
    for(int k = 0; k < 4; k++){ O0[k] = zero; O1[k] = zero; }

    for(int jt = js*JT_PER_SPLIT; jt < (js+1)*JT_PER_SPLIT; jt++){
        int j0 = jt * JTT;
        __syncthreads();
        for(int i4 = t; i4 < 144*8; i4 += 256){
            int c = i4 >> 3, jj = i4 & 7;
            *(float4*)(sK + c*SKP + jj*4) = *(const float4*)(Kg + (size_t)c*NSEQ + j0 + jj*4);
        }
        for(int i4 = t; i4 < 32*36; i4 += 256){
            int r = i4/36, c4 = i4%36;
            *(float4*)(sV + r*SVP + c4*4) = *(const float4*)(Vg + (size_t)(j0+r)*NCH + c4*4);
        }
        __syncthreads();

        ull S0 = zero, S1 = zero;
#pragma unroll 8
        for(int c = 0; c < NCH; c++){
            ull qa2 = *(const ull*)(sQd + c*SQDP + 2*r0);
            ull qb2 = *(const ull*)(sQd + c*SQDP + 2*r1);
            ull k2  = *(const ull*)(sK  + c*SKP  + tx*2);
            fma2(S0, qa2, k2);
            fma2(S1, qb2, k2);
        }
        float s00, s01, s10, s11;
        unpack2(S0, s00, s01);
        unpack2(S1, s10, s11);
        {
            float2 b0 = *(const float2*)(Bg + (size_t)r0*NSEQ + j0 + tx*2);
            float2 b1 = *(const float2*)(Bg + (size_t)r1*NSEQ + j0 + tx*2);
            s00 += b0.x; s01 += b0.y;
            s10 += b1.x; s11 += b1.y;
        }
        float nm0 = fmaxf(m0, grpMax(fmaxf(s00, s01)));
        float nm1 = fmaxf(m1, grpMax(fmaxf(s10, s11)));
        float a0 = __expf(m0 - nm0);
        float a1 = __expf(m1 - nm1);
        float p00 = __expf(s00-nm0), p01 = __expf(s01-nm0);
        float p10 = __expf(s10-nm1), p11 = __expf(s11-nm1);
        l0 = l0*a0 + grpSum(p00+p01);  m0 = nm0;
        l1 = l1*a1 + grpSum(p10+p11);  m1 = nm1;
        ull a02 = pack2(a0, a0), a12 = pack2(a1, a1);
#pragma unroll
        for(int k = 0; k < 4; k++){ mul2(O0[k], a02); mul2(O1[k], a12); }
        e0 *= a0; e1 *= a1;
        *(float2*)(sP + r0*SPP + tx*2) = make_float2(p00, p01);
        *(float2*)(sP + r1*SPP + tx*2) = make_float2(p10, p11);
        __syncthreads();

#pragma unroll 4
        for(int jj = 0; jj < JTT; jj++){
            float p0 = sP[r0*SPP + jj];
            float p1 = sP[r1*SPP + jj];
            ull pk0 = pack2(p0, p0);
            ull pk1 = pack2(p1, p1);
            const float* vr = sV + jj*SVP;
            ulonglong2 va = *(const ulonglong2*)(vr + tx*8);
            ulonglong2 vb = *(const ulonglong2*)(vr + tx*8 + 4);
            float vx = vr[128 + tx];
            fma2(O0[0], pk0, va.x); fma2(O0[1], pk0, va.y);
            fma2(O0[2], pk0, vb.x); fma2(O0[3], pk0, vb.y);
            fma2(O1[0], pk1, va.x); fma2(O1[1], pk1, va.y);
            fma2(O1[2], pk1, vb.x); fma2(O1[3], pk1, vb.y);
            e0 += p0*vx;
            e1 += p1*vx;
        }
    }

    // store unnormalized partials + (m, l)
    float* pg0 = g_part + (((size_t)js*16 + bh)*NSEQ + q0 + r0)*PART_STRIDE;
    float* pg1 = g_part + (((size_t)js*16 + bh)*NSEQ + q0 + r1)*PART_STRIDE;
    *(ulonglong2*)(pg0 + tx*8)     = make_ulonglong2(O0[0], O0[1]);
    *(ulonglong2*)(pg0 + tx*8 + 4) = make_ulonglong2(O0[2], O0[3]);
    pg0[128 + tx] = e0;
    *(ulonglong2*)(pg1 + tx*8)     = make_ulonglong2(O1[0], O1[1]);
    *(ulonglong2*)(pg1 + tx*8 + 4) = make_ulonglong2(O1[2], O1[3]);
    pg1[128 + tx] = e1;
    if(tx == 0){
        pg0[144] = m0; pg0[145] = l0;
        pg1[144] = m1; pg1[145] = l1;
    }
}

// ---------------- Kernel C2: combine split partials (flash merge) ----------------
// warp per (bh, q). grid 768 x 8 warps = 6144.
__global__ __launch_bounds__(256) void combine_kernel(){
    int t = threadIdx.x;
    int lane = t & 31, w = t >> 5;
    int bhq = blockIdx.x*8 + w;
    int bh = bhq / NSEQ, q = bhq % NSEQ;
    int b = bh >> 3, h = bh & 7;

    const float* P0 = g_part + (((size_t)0*16 + bh)*NSEQ + q)*PART_STRIDE;
    const float* P1 = g_part + (((size_t)1*16 + bh)*NSEQ + q)*PART_STRIDE;
    float m0 = P0[144], l0 = P0[145];
    float m1 = P1[144], l1 = P1[145];
    float M = fmaxf(m0, m1);
    float w0 = __expf(m0 - M), w1 = __expf(m1 - M);
    float inv = 1.0f / (l0*w0 + l1*w1);

    float* og = g_Hb + ((size_t)(b*NSEQ + q)*NH + h)*NCH;
#pragma unroll
    for(int k = 0; k < 5; k++){
        int ch = lane + 32*k;
        if(ch < NCH)
            og[ch] = (P0[ch]*w0 + P1[ch]*w1) * inv;
    }
}

// ---------------- Kernel D: output projections ----------------
__global__ __launch_bounds__(256) void out_kernel(
        const float* __restrict__ Wo_mv, const float* __restrict__ Wo_s,
        float* __restrict__ out){
    int bn = blockIdx.x;
    int t = threadIdx.x;
    __shared__ float wmv[16*64];
    __shared__ float ws [64*128];
    __shared__ float hrow[NH*NCH];

    for(int i = t; i < 1024; i += 256) wmv[i] = Wo_mv[i];
    for(int i4 = t; i4 < 2048; i4 += 256)
        *(float4*)(ws + i4*4) = ((const float4*)Wo_s)[i4];
    for(int i4 = t; i4 < 288; i4 += 256)
        *(float4*)(hrow + i4*4) = ((const float4*)(g_Hb + (size_t)bn*NH*NCH))[i4];
    __syncthreads();

    {
        int o = t >> 4, i = t & 15;
        float acc = 0.0f;
#pragma unroll
        for(int hh = 0; hh < 8; hh++)
#pragma unroll
            for(int mm = 0; mm < 8; mm++)
                acc += hrow[hh*NCH + mm*16 + i] * wmv[o*64 + hh*8 + mm];
        out[(size_t)bn*256 + t] = acc;
    }
    if(t < 64){
        float acc = 0.0f;
#pragma unroll
        for(int hh = 0; hh < 8; hh++)
#pragma unroll
            for(int ss = 0; ss < 16; ss++)
                acc += hrow[hh*NCH + 128 + ss] * ws[t*128 + hh*16 + ss];
        out[(size_t)NB*NSEQ*256 + (size_t)bn*64 + t] = acc;
    }
}

// ---------------- launch ----------------
extern "C" void kernel_launch(void* const* d_in, const int* in_sizes, int n_in,
                              void* d_out, int out_size){
    const float* mv    = (const float*)d_in[0];
    const float* sca   = (const float*)d_in[1];
    const float* pz    = (const float*)d_in[2];
    const unsigned int* mask = (const unsigned int*)d_in[3];
    const float* Wq_mv = (const float*)d_in[4];
    const float* Wq_s  = (const float*)d_in[5];
    const float* Wkv_mv= (const float*)d_in[6];
    const float* Wkv_s = (const float*)d_in[7];
    const float* Wo_mv = (const float*)d_in[8];
    const float* Wo_s  = (const float*)d_in[9];
    const float* lng   = (const float*)d_in[10];
    const float* lnb   = (const float*)d_in[11];
    const float* Wpb   = (const float*)d_in[12];

    cudaFuncSetAttribute(attn_kernel, cudaFuncAttributeMaxDynamicSharedMemorySize,
                         ATTN_SMEM_FLOATS * (int)sizeof(float));

    probe_kernel<<<1, 32>>>();
    qkv_kernel<<<NB*NSEQ, 256>>>(mv, sca, Wq_mv, Wq_s, Wkv_mv, Wkv_s);
    bias_kernel<<<(NB*NSEQ*NSEQ)/64, 256>>>(pz, mask, lng, lnb, Wpb);
    attn_kernel<<<dim3(NSEQ/QT, NB*NH, NSPLIT), 256, ATTN_SMEM_FLOATS*sizeof(float)>>>();
    combine_kernel<<<NB*NH*NSEQ/8, 256>>>();
    out_kernel<<<NB*NSEQ, 256>>>(Wo_mv, Wo_s, (float*)d_out);
}

// round 15
// speedup vs baseline: 2.0643x; 1.7024x over previous
#include <cuda_runtime.h>
#include <math.h>

#define NH 8
#define NB 2
#define NSEQ 384
#define NCZ 128
#define NCH 144            // per-head channels: 128 mv + 16 scalar
#define BIGF 100000.0f
#define LNEPS 1e-5f

#define QT 32              // q tile
#define JTT 64             // j tile
#define NJT (NSEQ/JTT)     // 6

// smem strides (floats)
#define SQP 36             // sQ [144][36]  (32 cols + pad, float4-aligned)
#define SKP 68             // sK [144][68]  (64 cols + pad, float4-aligned)
#define SVP 148            // sV [64][148]
#define SPP 68             // sP [32][68]
#define ATTN_SMEM_FLOATS (144*SQP + 144*SKP + 64*SVP + 32*SPP)

// Scratch (no cudaMalloc allowed)
__device__ float g_Q[NB*NH*NCH*NSEQ];    // channel-major [b][h][c][n]
__device__ float g_K[NB*NH*NCH*NSEQ];    // channel-major [b][h][c][n]
__device__ float g_V[NB*NH*NSEQ*NCH];    // row-major    [b][h][n][c]
__device__ float g_bias[NB*NH*NSEQ*NSEQ];
__device__ float g_Hb[NB*NSEQ*NH*NCH];

// ---------------- reductions ----------------
__device__ __forceinline__ float warpSum(float v){
#pragma unroll
    for(int o=16;o;o>>=1) v += __shfl_xor_sync(0xffffffffu, v, o);
    return v;
}

template<int NW>
__device__ __forceinline__ float blockSum(float v, float* red){
    int lane = threadIdx.x & 31, w = threadIdx.x >> 5;
    v = warpSum(v);
    if(lane==0) red[w] = v;
    __syncthreads();
    if(threadIdx.x < 32){
        float r = (lane < NW) ? red[lane] : 0.0f;
        r = warpSum(r);
        if(lane==0) red[0] = r;
    }
    __syncthreads();
    float r = red[0];
    __syncthreads();
    return r;
}

// reduce over the 16-lane tx-group (lanes with same ty)
__device__ __forceinline__ float grpMax(float v){
#pragma unroll
    for(int o=8;o;o>>=1) v = fmaxf(v, __shfl_xor_sync(0xffffffffu, v, o));
    return v;
}
__device__ __forceinline__ float grpSum(float v){
#pragma unroll
    for(int o=8;o;o>>=1) v += __shfl_xor_sync(0xffffffffu, v, o);
    return v;
}

// ---------------- probes: 2 probes put the ncu capture slot on bias_kernel ----------------
__global__ void probe_kernel(){}
__global__ void probe_kernel2(){}

// ---------------- Kernel A: pln + QKV projections + rope ----------------
__global__ void qkv_kernel(const float* __restrict__ mv, const float* __restrict__ sca,
                           const float* __restrict__ Wq_mv, const float* __restrict__ Wq_s,
                           const float* __restrict__ Wkv_mv, const float* __restrict__ Wkv_s){
    int bn = blockIdx.x;
    int b = bn / NSEQ, n = bn % NSEQ;
    int t = threadIdx.x;
    __shared__ float mvn[256];
    __shared__ float scn[64];
    __shared__ float qs[128], ks[128], vs[128];
    __shared__ float red[32];
    const float scl = 1.0f/12.0f;  // 1/sqrt(144)

    float x = mv[(size_t)bn*256 + t];
    float s1 = blockSum<8>(x, red);
    float s2 = blockSum<8>(x*x, red);
    float m  = s1 * (1.0f/256.0f);
    float vr = s2 * (1.0f/256.0f) - m*m;
    mvn[t] = (x - m) * rsqrtf(vr + LNEPS);

    float y = (t < 64) ? sca[(size_t)bn*64 + t] : 0.0f;
    float t1 = blockSum<8>(y, red);
    float t2 = blockSum<8>(y*y, red);
    float m2 = t1 * (1.0f/64.0f);
    float v2 = t2 * (1.0f/64.0f) - m2*m2;
    float rs2 = rsqrtf(v2 + LNEPS);
    if(t < 64) scn[t] = (y - m2) * rs2;
    __syncthreads();

    // q_mv -> g_Q channel-major
    for(int idx = t; idx < 1024; idx += 256){
        int o = idx >> 4, i = idx & 15;
        float a = 0.0f;
#pragma unroll
        for(int c = 0; c < 16; c++) a += mvn[c*16 + i] * Wq_mv[o*16 + c];
        int hh = o & 7, mm = o >> 3;
        g_Q[((size_t)(b*NH + hh)*NCH + mm*16 + i)*NSEQ + n] = a * scl;
    }
    // kv_mv -> g_K channel-major, g_V row-major
    for(int idx = t; idx < 2048; idx += 256){
        int o = idx >> 4, i = idx & 15;
        float a = 0.0f;
#pragma unroll
        for(int c = 0; c < 16; c++) a += mvn[c*16 + i] * Wkv_mv[o*16 + c];
        int kv = o >> 6, rr = o & 63, hh = rr & 7, mm = rr >> 3;
        if(kv == 0) g_K[((size_t)(b*NH + hh)*NCH + mm*16 + i)*NSEQ + n] = a;
        else        g_V[((size_t)(b*NH + hh)*NSEQ + n)*NCH + mm*16 + i] = a;
    }
    if(t < 128){
        float a = 0.0f;
#pragma unroll
        for(int c = 0; c < 64; c++) a += scn[c] * Wq_s[t*64 + c];
        qs[t] = a;
    }
    {
        float a = 0.0f;
#pragma unroll
        for(int c = 0; c < 64; c++) a += scn[c] * Wkv_s[t*64 + c];
        int kv = t >> 7, rr = t & 127;
        if(kv == 0) ks[rr] = a; else vs[rr] = a;
    }
    __syncthreads();

    if(t < 128){
        int hh = t & 7, ss = t >> 3;
        g_V[((size_t)(b*NH + hh)*NSEQ + n)*NCH + 128 + ss] = vs[t];
    }
    if(t < 64){
        int hh = t & 7, p = t >> 3;
        float ang = (float)n * exp2f(-1.5f * (float)p);
        float cs = cosf(ang), sn = sinf(ang);
        float x1 = qs[(2*p)*8 + hh], x2 = qs[(2*p+1)*8 + hh];
        size_t base = ((size_t)(b*NH + hh)*NCH + 128);
        g_Q[(base + 2*p  )*NSEQ + n] = (x1*cs - x2*sn) * scl;
        g_Q[(base + 2*p+1)*NSEQ + n] = (x1*sn + x2*cs) * scl;
    } else if(t < 128){
        int u = t - 64;
        int hh = u & 7, p = u >> 3;
        float ang = (float)n * exp2f(-1.5f * (float)p);
        float cs = cosf(ang), sn = sinf(ang);
        float x1 = ks[(2*p)*8 + hh], x2 = ks[(2*p+1)*8 + hh];
        size_t base = ((size_t)(b*NH + hh)*NCH + 128);
        g_K[(base + 2*p  )*NSEQ + n] = x1*cs - x2*sn;
        g_K[(base + 2*p+1)*NSEQ + n] = x1*sn + x2*cs;
    }
}

// ---------------- Kernel B: bias (R8 tiled version, the 303us config) ----------------
__global__ __launch_bounds__(256) void bias_kernel(
        const float* __restrict__ pz, const unsigned int* __restrict__ msk,
        const float* __restrict__ gamma, const float* __restrict__ beta,
        const float* __restrict__ Wpb){
    __shared__ float sZ[32*132];
    __shared__ float sA[8*132];
    __shared__ float sG[8], sB[8];
    __shared__ float sM[32];
    __shared__ float sR[32];
    __shared__ float sMask[32];

    int t = threadIdx.x;
    int lane = t & 31, w = t >> 5;
    int pid0 = blockIdx.x * 32;
    int b  = pid0 / (NSEQ*NSEQ);
    int r0 = pid0 % (NSEQ*NSEQ);
    int i  = r0 / NSEQ;
    int j0 = r0 % NSEQ;

    const float4* zg = (const float4*)(pz + (size_t)pid0 * NCZ);
    for(int i4 = t; i4 < 1024; i4 += 256){
        int r = i4 >> 5, c4 = i4 & 31;
        *(float4*)(sZ + r*132 + c4*4) = zg[i4];
    }
    for(int idx = t; idx < 1024; idx += 256){
        int h = idx >> 7, c = idx & 127;
        sA[h*132 + c] = gamma[c] * Wpb[h*NCZ + c];
    }
    {
        float gs = 0.f, bs = 0.f;
#pragma unroll
        for(int k = 0; k < 4; k++){
            int c = lane + 32*k;
            float wv = Wpb[w*NCZ + c];
            gs += gamma[c]*wv;
            bs += beta[c]*wv;
        }
        gs = warpSum(gs); bs = warpSum(bs);
        if(lane == 0){ sG[w] = gs; sB[w] = bs; }
    }
    if(t < 32) sMask[t] = (msk[pid0 + t] != 0u) ? 0.0f : BIGF;
    __syncthreads();

#pragma unroll
    for(int rr = 0; rr < 4; rr++){
        int p = w*4 + rr;
        float4 z4 = *(const float4*)(sZ + p*132 + lane*4);
        float s1 = z4.x + z4.y + z4.z + z4.w;
        float s2 = z4.x*z4.x + z4.y*z4.y + z4.z*z4.z + z4.w*z4.w;
        s1 = warpSum(s1); s2 = warpSum(s2);
        if(lane == 0){
            float m = s1 * (1.0f/NCZ);
            float v = s2 * (1.0f/NCZ) - m*m;
            sM[p] = m;
            sR[p] = rsqrtf(v + LNEPS);
        }
    }
    __syncthreads();

    {
        int p = t >> 3, h = t & 7;
        const float4* zp = (const float4*)(sZ + p*132);
        const float4* ap = (const float4*)(sA + h*132);
        float acc = 0.f;
#pragma unroll
        for(int c4 = 0; c4 < 32; c4++){
            float4 z4 = zp[c4], a4 = ap[c4];
            acc += z4.x*a4.x + z4.y*a4.y + z4.z*a4.z + z4.w*a4.w;
        }
        float out = sR[p]*(acc - sM[p]*sG[h]) + sB[h] + sMask[p];
        g_bias[((size_t)(b*NH + h)*NSEQ + i)*NSEQ + j0 + p] = out;
    }
}

// ---------------- Kernel C: attention (R8 outer-product body, best measured) ----------------
// Block per (b,h,qtile32). 256 threads = (ty 0..15) x (tx 0..15).
__global__ __launch_bounds__(256, 2) void attn_kernel(){
    extern __shared__ float smem[];
    float* sQ = smem;                       // [144][SQP]
    float* sK = sQ + 144*SQP;               // [144][SKP]
    float* sV = sK + 144*SKP;               // [64][SVP]
    float* sP = sV + 64*SVP;                // [32][SPP]

    int qt = blockIdx.x, h = blockIdx.y, b = blockIdx.z;
    int t = threadIdx.x;
    int ty = t >> 4, tx = t & 15;
    int q0 = qt * QT;
    size_t bh = (size_t)(b*NH + h);

    const float* Qg = g_Q + bh*NCH*NSEQ;    // [c][n]
    const float* Kg = g_K + bh*NCH*NSEQ;    // [c][n]
    const float* Vg = g_V + bh*NSEQ*NCH;    // [n][c]
    const float* Bg = g_bias + (bh*NSEQ + q0)*NSEQ;

    // load Q tile: 144 ch x 32 q
    for(int i4 = t; i4 < 144*8; i4 += 256){
        int c = i4 >> 3, qq = i4 & 7;
        *(float4*)(sQ + c*SQP + qq*4) = *(const float4*)(Qg + (size_t)c*NSEQ + q0 + qq*4);
    }

    int r0 = ty*2, r1 = ty*2 + 1;
    float m0 = -1e30f, m1 = -1e30f, l0 = 0.f, l1 = 0.f;
    float O0[9], O1[9];
#pragma unroll
    for(int k = 0; k < 9; k++){ O0[k]=0.f; O1[k]=0.f; }

    for(int jt = 0; jt < NJT; jt++){
        int j0 = jt * JTT;
        __syncthreads();   // previous AV done before overwriting K/V
        // K tile: 144 ch x 64 j
        for(int i4 = t; i4 < 144*16; i4 += 256){
            int c = i4 >> 4, jj = i4 & 15;
            *(float4*)(sK + c*SKP + jj*4) = *(const float4*)(Kg + (size_t)c*NSEQ + j0 + jj*4);
        }
        // V tile: 64 j x 144 ch
        for(int i4 = t; i4 < 64*36; i4 += 256){
            int r = i4/36, c4 = i4%36;
            *(float4*)(sV + r*SVP + c4*4) = *(const float4*)(Vg + (size_t)(j0+r)*NCH + c4*4);
        }
        __syncthreads();

        // S: 2x4 per thread, outer product over channels
        float s00=0,s01=0,s02=0,s03=0,s10=0,s11=0,s12=0,s13=0;
#pragma unroll 8
        for(int c = 0; c < NCH; c++){
            float qa = sQ[c*SQP + r0];
            float qb = sQ[c*SQP + r1];
            float4 k4 = *(float4*)(sK + c*SKP + tx*4);
            s00 += qa*k4.x; s01 += qa*k4.y; s02 += qa*k4.z; s03 += qa*k4.w;
            s10 += qb*k4.x; s11 += qb*k4.y; s12 += qb*k4.z; s13 += qb*k4.w;
        }
        {
            float4 b0 = *(const float4*)(Bg + (size_t)r0*NSEQ + j0 + tx*4);
            float4 b1 = *(const float4*)(Bg + (size_t)r1*NSEQ + j0 + tx*4);
            s00+=b0.x; s01+=b0.y; s02+=b0.z; s03+=b0.w;
            s10+=b1.x; s11+=b1.y; s12+=b1.z; s13+=b1.w;
        }
        // online softmax update
        float nm0 = grpMax(fmaxf(fmaxf(s00,s01), fmaxf(s02,s03)));
        float nm1 = grpMax(fmaxf(fmaxf(s10,s11), fmaxf(s12,s13)));
        nm0 = fmaxf(m0, nm0);
        nm1 = fmaxf(m1, nm1);
        float a0 = __expf(m0 - nm0);
        float a1 = __expf(m1 - nm1);
        float p00 = __expf(s00-nm0), p01 = __expf(s01-nm0), p02 = __expf(s02-nm0), p03 = __expf(s03-nm0);
        float p10 = __expf(s10-nm1), p11 = __expf(s11-nm1), p12 = __expf(s12-nm1), p13 = __expf(s13-nm1);
        float ps0 = grpSum(p00+p01+p02+p03);
        float ps1 = grpSum(p10+p11+p12+p13);
        l0 = l0*a0 + ps0;  m0 = nm0;
        l1 = l1*a1 + ps1;  m1 = nm1;
#pragma unroll
        for(int k = 0; k < 9; k++){ O0[k] *= a0; O1[k] *= a1; }
        *(float4*)(sP + r0*SPP + tx*4) = make_float4(p00,p01,p02,p03);
        *(float4*)(sP + r1*SPP + tx*4) = make_float4(p10,p11,p12,p13);
        __syncthreads();

        // AV: accumulate over the 64 keys of this tile
#pragma unroll 4
        for(int jj = 0; jj < JTT; jj++){
            float p0 = sP[r0*SPP + jt*0 + jj];
            float p1 = sP[r1*SPP + jj];
            const float* vr = sV + jj*SVP + tx*9;
#pragma unroll
            for(int k = 0; k < 9; k++){
                float vv = vr[k];
                O0[k] += p0*vv;
                O1[k] += p1*vv;
            }
        }
    }

    float inv0 = 1.0f/l0, inv1 = 1.0f/l1;
    float* o0 = g_Hb + ((size_t)(b*NSEQ + q0 + r0)*NH + h)*NCH + tx*9;
    float* o1 = g_Hb + ((size_t)(b*NSEQ + q0 + r1)*NH + h)*NCH + tx*9;
#pragma unroll
    for(int k = 0; k < 9; k++){ o0[k] = O0[k]*inv0; o1[k] = O1[k]*inv1; }
}

// ---------------- Kernel D: output projections ----------------
__global__ __launch_bounds__(256) void out_kernel(
        const float* __restrict__ Wo_mv, const float* __restrict__ Wo_s,
        float* __restrict__ out){
    int bn = blockIdx.x;
    int t = threadIdx.x;
    __shared__ float wmv[16*64];
    __shared__ float ws [64*128];
    __shared__ float hrow[NH*NCH];

    for(int i = t; i < 1024; i += 256) wmv[i] = Wo_mv[i];
    for(int i4 = t; i4 < 2048; i4 += 256)
        *(float4*)(ws + i4*4) = ((const float4*)Wo_s)[i4];
    for(int i4 = t; i4 < 288; i4 += 256)
        *(float4*)(hrow + i4*4) = ((const float4*)(g_Hb + (size_t)bn*NH*NCH))[i4];
    __syncthreads();

    {
        int o = t >> 4, i = t & 15;
        float acc = 0.0f;
#pragma unroll
        for(int hh = 0; hh < 8; hh++)
#pragma unroll
            for(int mm = 0; mm < 8; mm++)
                acc += hrow[hh*NCH + mm*16 + i] * wmv[o*64 + hh*8 + mm];
        out[(size_t)bn*256 + t] = acc;
    }
    if(t < 64){
        float acc = 0.0f;
#pragma unroll
        for(int hh = 0; hh < 8; hh++)
#pragma unroll
            for(int ss = 0; ss < 16; ss++)
                acc += hrow[hh*NCH + 128 + ss] * ws[t*128 + hh*16 + ss];
        out[(size_t)NB*NSEQ*256 + (size_t)bn*64 + t] = acc;
    }
}

// ---------------- launch ----------------
extern "C" void kernel_launch(void* const* d_in, const int* in_sizes, int n_in,
                              void* d_out, int out_size){
    const float* mv    = (const float*)d_in[0];
    const float* sca   = (const float*)d_in[1];
    const float* pz    = (const float*)d_in[2];
    const unsigned int* mask = (const unsigned int*)d_in[3];
    const float* Wq_mv = (const float*)d_in[4];
    const float* Wq_s  = (const float*)d_in[5];
    const float* Wkv_mv= (const float*)d_in[6];
    const float* Wkv_s = (const float*)d_in[7];
    const float* Wo_mv = (const float*)d_in[8];
    const float* Wo_s  = (const float*)d_in[9];
    const float* lng   = (const float*)d_in[10];
    const float* lnb   = (const float*)d_in[11];
    const float* Wpb   = (const float*)d_in[12];

    cudaFuncSetAttribute(attn_kernel, cudaFuncAttributeMaxDynamicSharedMemorySize,
                         ATTN_SMEM_FLOATS * (int)sizeof(float));

    probe_kernel<<<1, 32>>>();    // two probes: ncu capture (4th kernel) lands on bias
    probe_kernel2<<<1, 32>>>();
    qkv_kernel<<<NB*NSEQ, 256>>>(mv, sca, Wq_mv, Wq_s, Wkv_mv, Wkv_s);
    bias_kernel<<<(NB*NSEQ*NSEQ)/32, 256>>>(pz, mask, lng, lnb, Wpb);
    attn_kernel<<<dim3(NSEQ/QT, NH, NB), 256, ATTN_SMEM_FLOATS*sizeof(float)>>>();
    out_kernel<<<NB*NSEQ, 256>>>(Wo_mv, Wo_s, (float*)d_out);
}